// round 6
// baseline (speedup 1.0000x reference)
#include <cuda_runtime.h>
#include <cuda_bf16.h>

#define NB 64      // batch
#define TT 512     // timesteps
#define DD 512     // input size
#define HH 512     // hidden size

#define GROUPS 4           // m-groups (16 batch rows each) -- independent recurrences
#define SUBS 32            // n-CTAs per group
#define SCAN_CTAS (GROUPS * SUBS)   // 128
#define SCAN_NT 16         // hidden columns per CTA
#define MROWS 16           // batch rows per group
#define HSTRIDE 520        // 512 + 8 pad halves (16B-aligned rows, conflict-free LDSM)

// ---------------- scratch (device globals; no allocation allowed) ----------
__device__ __align__(16) __nv_bfloat16 g_hh[2][NB * HH];  // h hi, double buffered
__device__ __align__(16) __nv_bfloat16 g_hl[2][NB * HH];  // h lo
// per (group, k-quarter) arrival counters, one 128B line each: 16 lines
__device__ __align__(128) unsigned g_cnt[16 * 32];

// ---------------- helpers --------------------------------------------------
__device__ __forceinline__ void split2(float v, __nv_bfloat16 &hi, __nv_bfloat16 &lo) {
    hi = __float2bfloat16(v);
    lo = __float2bfloat16(v - __bfloat162float(hi));
}

__device__ __forceinline__ void mma4(float *c, unsigned a0, unsigned a1, unsigned a2,
                                     unsigned a3, unsigned b0, unsigned b1) {
    asm volatile(
        "mma.sync.aligned.m16n8k16.row.col.f32.bf16.bf16.f32 "
        "{%0,%1,%2,%3}, {%4,%5,%6,%7}, {%8,%9}, {%0,%1,%2,%3};\n"
        : "+f"(c[0]), "+f"(c[1]), "+f"(c[2]), "+f"(c[3])
        : "r"(a0), "r"(a1), "r"(a2), "r"(a3), "r"(b0), "r"(b1));
}

__device__ __forceinline__ void ldsm_x4(unsigned &r0, unsigned &r1, unsigned &r2,
                                        unsigned &r3, unsigned addr) {
    asm volatile("ldmatrix.sync.aligned.m8n8.x4.shared.b16 {%0,%1,%2,%3}, [%4];"
                 : "=r"(r0), "=r"(r1), "=r"(r2), "=r"(r3)
                 : "r"(addr));
}

__device__ __forceinline__ void cp16(void *dst_smem, const void *src) {
    unsigned d = (unsigned)__cvta_generic_to_shared(dst_smem);
    asm volatile("cp.async.cg.shared.global [%0], [%1], 16;" :: "r"(d), "l"(src));
}

__device__ __forceinline__ float fast_tanh(float x) {
    float e = __expf(2.0f * x);
    return 1.0f - __fdividef(2.0f, e + 1.0f);
}

// ---------------- kernel 1: xWx = x @ Wx + b  -> out ------------------------
// CTA tile 128x64, BK=32, 256 threads. Fragments via ldmatrix. (unchanged)
__global__ __launch_bounds__(256) void gemm_xwx_kernel(
    const float *__restrict__ x, const float *__restrict__ Wx,
    const float *__restrict__ b, float *__restrict__ out) {

    __shared__ __align__(16) __nv_bfloat16 Ah[128 * 40];
    __shared__ __align__(16) __nv_bfloat16 Al[128 * 40];
    __shared__ __align__(16) __nv_bfloat16 Bh[64 * 40];
    __shared__ __align__(16) __nv_bfloat16 Bl[64 * 40];

    const int tid  = threadIdx.x;
    const int warp = tid >> 5;
    const int lane = tid & 31;
    const int g    = lane >> 2;
    const int tg   = lane & 3;
    const int wm   = warp >> 1;
    const int wn   = warp & 1;
    const int row0 = blockIdx.x * 128;
    const int col0 = blockIdx.y * 64;

    const int quad = lane >> 3, lrow = lane & 7;
    unsigned aHaddr[2], aLaddr[2], bAddr[4];
#pragma unroll
    for (int mt = 0; mt < 2; mt++) {
        int r = wm * 32 + mt * 16 + (quad & 1) * 8 + lrow;
        int off = r * 40 + (quad >> 1) * 8;
        aHaddr[mt] = (unsigned)__cvta_generic_to_shared(Ah + off);
        aLaddr[mt] = (unsigned)__cvta_generic_to_shared(Al + off);
    }
#pragma unroll
    for (int nt = 0; nt < 4; nt++) {
        int r = wn * 32 + nt * 8 + lrow;
        const __nv_bfloat16 *base = (quad < 2) ? Bh : Bl;
        bAddr[nt] = (unsigned)__cvta_generic_to_shared(base + r * 40 + (quad & 1) * 8);
    }

    float acc[2][4][4];
#pragma unroll
    for (int mt = 0; mt < 2; mt++)
#pragma unroll
        for (int nt = 0; nt < 4; nt++)
#pragma unroll
            for (int i = 0; i < 4; i++) acc[mt][nt][i] = 0.0f;

    for (int k0 = 0; k0 < DD; k0 += 32) {
        __syncthreads();
#pragma unroll
        for (int i = 0; i < 16; i++) {
            int idx = tid + i * 256;
            int r = idx >> 5, c = idx & 31;
            float v = x[(size_t)(row0 + r) * DD + k0 + c];
            __nv_bfloat16 hi, lo; split2(v, hi, lo);
            Ah[r * 40 + c] = hi; Al[r * 40 + c] = lo;
        }
#pragma unroll
        for (int i = 0; i < 8; i++) {
            int idx = tid + i * 256;
            int nn = idx & 63, kk = idx >> 6;
            float v = Wx[(size_t)(k0 + kk) * HH + col0 + nn];
            __nv_bfloat16 hi, lo; split2(v, hi, lo);
            Bh[nn * 40 + kk] = hi; Bl[nn * 40 + kk] = lo;
        }
        __syncthreads();

#pragma unroll
        for (int ks = 0; ks < 2; ks++) {
            const unsigned off = ks * 32;   // 16 halves = 32 bytes
            unsigned bfr[4][4];
#pragma unroll
            for (int nt = 0; nt < 4; nt++)
                ldsm_x4(bfr[nt][0], bfr[nt][1], bfr[nt][2], bfr[nt][3], bAddr[nt] + off);
#pragma unroll
            for (int mt = 0; mt < 2; mt++) {
                unsigned a0, a1, a2, a3, l0, l1, l2, l3;
                ldsm_x4(a0, a1, a2, a3, aHaddr[mt] + off);
                ldsm_x4(l0, l1, l2, l3, aLaddr[mt] + off);
#pragma unroll
                for (int nt = 0; nt < 4; nt++) {
                    mma4(acc[mt][nt], a0, a1, a2, a3, bfr[nt][0], bfr[nt][1]);
                    mma4(acc[mt][nt], a0, a1, a2, a3, bfr[nt][2], bfr[nt][3]);
                    mma4(acc[mt][nt], l0, l1, l2, l3, bfr[nt][0], bfr[nt][1]);
                }
            }
        }
    }

#pragma unroll
    for (int mt = 0; mt < 2; mt++)
#pragma unroll
        for (int nt = 0; nt < 4; nt++) {
            int r = row0 + wm * 32 + mt * 16 + g;
            int c = col0 + wn * 32 + nt * 8 + tg * 2;
            float b0 = b[c], b1 = b[c + 1];
            out[(size_t)r * HH + c]           = acc[mt][nt][0] + b0;
            out[(size_t)r * HH + c + 1]       = acc[mt][nt][1] + b1;
            out[(size_t)(r + 8) * HH + c]     = acc[mt][nt][2] + b0;
            out[(size_t)(r + 8) * HH + c + 1] = acc[mt][nt][3] + b1;
        }
}

// ---------------- counter reset (per graph replay determinism) --------------
__global__ void reset_bar_kernel() {
    int i = threadIdx.x;
    if (i < 16 * 32) g_cnt[i] = 0;
}

// ---------------- kernel 2: persistent recurrent scan -----------------------
// 128 CTAs = 4 independent m-groups x 32 n-CTAs (16 cols each).
// Fine-grained sync: per (group, k-quarter) counters with 8 publishers each.
// Warp-pair kq polls only its quarter, stages only its 8KB slice, and starts
// MMA while later quarters' producers are still publishing.
__global__ __launch_bounds__(256) void rnn_scan_kernel(
    const float *__restrict__ h0, const float *__restrict__ Wh,
    float *__restrict__ out) {

    extern __shared__ __nv_bfloat16 smem[];
    __nv_bfloat16 *Hh  = smem;                        // 16 x 520
    __nv_bfloat16 *Hl  = Hh + MROWS * HSTRIDE;        // 16 x 520
    __nv_bfloat16 *Wsh = Hl + MROWS * HSTRIDE;        // 16 x 520
    __nv_bfloat16 *Wsl = Wsh + SCAN_NT * HSTRIDE;     // 16 x 520
    __shared__ float redbuf[4][16][16];               // per-quarter partials

    const int tid   = threadIdx.x;
    const int warp  = tid >> 5;
    const int lane  = tid & 31;
    const int g     = lane >> 2;
    const int tg    = lane & 3;
    const int group = blockIdx.x >> 5;
    const int sub   = blockIdx.x & 31;
    const int cb    = sub * SCAN_NT;
    const int rbase = group * MROWS;
    const int kq    = warp >> 1;        // K-quarter 0..3
    const int ntile = warp & 1;         // n8 tile 0..1
    const int kb    = kq * 128;         // K offset in elements

    unsigned *cnt_poll = &g_cnt[(group * 4 + kq) * 32];          // consumed quarter
    unsigned *cnt_pub  = &g_cnt[(group * 4 + (sub >> 3)) * 32];  // published quarter

    // resident Wh slice: Wsh[n][k] = Wh[k][cb+n], split hi/lo
    for (int idx = tid; idx < HH * SCAN_NT; idx += 256) {
        int n = idx & (SCAN_NT - 1), k = idx >> 4;
        float v = Wh[(size_t)k * HH + cb + n];
        __nv_bfloat16 hi, lo; split2(v, hi, lo);
        Wsh[n * HSTRIDE + k] = hi; Wsl[n * HSTRIDE + k] = lo;
    }

    // ldmatrix lane addresses (constant across steps)
    const int quad = lane >> 3, lrow = lane & 7;
    const int aRow = (quad & 1) * 8 + lrow;
    const int aCol = kb + (quad >> 1) * 8;
    const unsigned addrAh = (unsigned)__cvta_generic_to_shared(Hh + aRow * HSTRIDE + aCol);
    const unsigned addrAl = (unsigned)__cvta_generic_to_shared(Hl + aRow * HSTRIDE + aCol);
    const __nv_bfloat16 *bbase = (quad < 2) ? Wsh : Wsl;
    const unsigned addrB = (unsigned)__cvta_generic_to_shared(
        bbase + (ntile * 8 + lrow) * HSTRIDE + kb + (quad & 1) * 8);

    // distributed-epilogue mapping: one output value per thread
    const int em = tid >> 4;            // 0..15 batch row within group
    const int ec = tid & 15;            // 0..15 column within CTA slice
    const size_t out_idx_base = ((size_t)(rbase + em) * TT) * HH + cb + ec;
    const int h_idx = (rbase + em) * HH + cb + ec;

    for (int t = 0; t < TT; t++) {
        // ---- prefetch xwx (independent of recurrence dataflow) ----
        float xw = out[out_idx_base + (size_t)t * HH];

        if (t == 0) {
            // stage full h0 with split conversion (all threads)
#pragma unroll
            for (int i = 0; i < 8; i++) {
                int idx = tid + i * 256;          // 2048 float4
                int r = idx >> 7, c4i = idx & 127;
                float4 v = ((const float4 *)(h0 + (size_t)(rbase + r) * HH))[c4i];
                __nv_bfloat16 hx, lx, hy, ly, hz, lz, hw, lw;
                split2(v.x, hx, lx); split2(v.y, hy, ly);
                split2(v.z, hz, lz); split2(v.w, hw, lw);
                __nv_bfloat162 ph01 = {hx, hy}, ph23 = {hz, hw};
                __nv_bfloat162 pl01 = {lx, ly}, pl23 = {lz, lw};
                uint2 uh = {*(unsigned *)&ph01, *(unsigned *)&ph23};
                uint2 ul = {*(unsigned *)&pl01, *(unsigned *)&pl23};
                ((uint2 *)(Hh + r * HSTRIDE))[c4i] = uh;
                ((uint2 *)(Hl + r * HSTRIDE))[c4i] = ul;
            }
            __syncthreads();
        } else {
            // per-warp: wait for the 8 CTAs producing this k-quarter
            if (lane == 0) {
                const unsigned target = (unsigned)(8 * t);
                unsigned v;
                do {
                    asm volatile("ld.acquire.gpu.global.u32 %0, [%1];"
                                 : "=r"(v) : "l"(cnt_poll) : "memory");
                } while (v < target);
            }
            __syncwarp();

            // stage this quarter's slice: ntile0 -> Hh, ntile1 -> Hl (4KB each)
            const __nv_bfloat16 *src =
                (ntile ? g_hl[(t - 1) & 1] : g_hh[(t - 1) & 1]) + (size_t)rbase * HH;
            __nv_bfloat16 *dst = ntile ? Hl : Hh;
#pragma unroll
            for (int i = 0; i < 8; i++) {
                int idx = i * 32 + lane;          // 256 x 16B chunks
                int r = idx >> 4, c = idx & 15;
                cp16(dst + r * HSTRIDE + kb + c * 8, src + r * HH + kb + c * 8);
            }
            asm volatile("cp.async.commit_group;");
            asm volatile("cp.async.wait_group 0;");
            asm volatile("bar.sync %0, 64;" :: "r"(2 + kq) : "memory");  // pair barrier
        }

        // ---- k-loop: 8 x k16 per warp, split-bf16 3-term ----
        float c4[4] = {0.f, 0.f, 0.f, 0.f};
#pragma unroll
        for (int kk = 0; kk < 8; kk++) {
            const unsigned off = kk * 32;  // 16 halves = 32 bytes
            unsigned a0, a1, a2, a3, l0, l1, l2, l3, b0, b1, b2, b3;
            ldsm_x4(a0, a1, a2, a3, addrAh + off);
            ldsm_x4(l0, l1, l2, l3, addrAl + off);
            ldsm_x4(b0, b1, b2, b3, addrB + off);
            mma4(c4, a0, a1, a2, a3, b0, b1);   // Ah*Bh
            mma4(c4, a0, a1, a2, a3, b2, b3);   // Ah*Bl
            mma4(c4, l0, l1, l2, l3, b0, b1);   // Al*Bh
        }

        // ---- all quarters write partials ----
        {
            const int cc = ntile * 8 + tg * 2;
            *(float2 *)&redbuf[kq][g][cc]     = make_float2(c4[0], c4[1]);
            *(float2 *)&redbuf[kq][g + 8][cc] = make_float2(c4[2], c4[3]);
        }
        __syncthreads();

        // ---- distributed epilogue: one value per thread ----
        {
            float v = redbuf[0][em][ec] + redbuf[1][em][ec] +
                      redbuf[2][em][ec] + redbuf[3][em][ec] + xw;
            float hv = fast_tanh(v);
            out[out_idx_base + (size_t)t * HH] = hv;
            __nv_bfloat16 hi, lo; split2(hv, hi, lo);
            g_hh[t & 1][h_idx] = hi;
            g_hl[t & 1][h_idx] = lo;
        }
        __syncthreads();

        if (tid == 0 && t < TT - 1) {
            // fire-and-forget arrival for this CTA's quarter
            asm volatile("red.release.gpu.global.add.u32 [%0], %1;"
                         :: "l"(cnt_pub), "r"(1u) : "memory");
        }
    }
}

// ---------------- launch ----------------------------------------------------
extern "C" void kernel_launch(void *const *d_in, const int *in_sizes, int n_in,
                              void *d_out, int out_size) {
    const float *x  = (const float *)d_in[0];   // (64, 512, 512)
    const float *h0 = (const float *)d_in[1];   // (64, 512)
    const float *Wx = (const float *)d_in[2];   // (512, 512)
    const float *Wh = (const float *)d_in[3];   // (512, 512)
    const float *b  = (const float *)d_in[4];   // (512,)
    float *out = (float *)d_out;                // (64, 512, 512)

    const int scan_smem =
        (2 * MROWS * HSTRIDE + 2 * SCAN_NT * HSTRIDE) * (int)sizeof(__nv_bfloat16);
    cudaFuncSetAttribute(rnn_scan_kernel,
                         cudaFuncAttributeMaxDynamicSharedMemorySize, scan_smem);

    dim3 grid1(NB * TT / 128, HH / 64);
    gemm_xwx_kernel<<<grid1, 256>>>(x, Wx, b, out);
    reset_bar_kernel<<<1, 512>>>();
    rnn_scan_kernel<<<SCAN_CTAS, 256, scan_smem>>>(h0, Wh, out);
}